// round 9
// baseline (speedup 1.0000x reference)
#include <cuda_runtime.h>
#include <cuda_bf16.h>
#include <math.h>
#include <cstdint>

#define S_DIM 4096
#define B_DIM 64
#define E_DIM 512
#define V_DIM 512

// Scratch (allocation-free rule: __device__ globals)
__device__ float g_scores[B_DIM * S_DIM];     // [b][s] layout (coalesced softmax reads)
__device__ float g_attn_bs[B_DIM * S_DIM];    // [b][s] attn copy for context kernel
__device__ __align__(16) float g_pqb[B_DIM * E_DIM];
__device__ __align__(16) float g_nv[E_DIM];
__device__ __align__(128) __nv_bfloat16 g_WvB[E_DIM * V_DIM];

// ======================= helpers =======================
__device__ __forceinline__ uint32_t smem_u32(const void* p) {
    uint32_t a;
    asm("{ .reg .u64 t; cvta.to.shared.u64 t, %1; cvt.u32.u64 %0, t; }" : "=r"(a) : "l"(p));
    return a;
}
__device__ __forceinline__ float tanh_fast(float x) {
    float y; asm("tanh.approx.f32 %0, %1;" : "=f"(y) : "f"(x)); return y;
}
__device__ __forceinline__ unsigned pk2(float x, float y) {
    __nv_bfloat162 h = __floats2bfloat162_rn(x, y);
    return reinterpret_cast<unsigned&>(h);
}
__device__ __forceinline__ void cpa16(uint32_t dst, const void* src) {
    asm volatile("cp.async.cg.shared.global [%0], [%1], 16;" :: "r"(dst), "l"(src) : "memory");
}
__device__ __forceinline__ void mma_bf16(float c[4], const unsigned a[4], unsigned b0, unsigned b1) {
    asm volatile("mma.sync.aligned.m16n8k16.row.col.f32.bf16.bf16.f32 "
                 "{%0,%1,%2,%3}, {%4,%5,%6,%7}, {%8,%9}, {%0,%1,%2,%3};"
                 : "+f"(c[0]), "+f"(c[1]), "+f"(c[2]), "+f"(c[3])
                 : "r"(a[0]), "r"(a[1]), "r"(a[2]), "r"(a[3]), "r"(b0), "r"(b1));
}
#define LDSM4(r, a) \
    asm volatile("ldmatrix.sync.aligned.m8n8.x4.shared.b16 {%0,%1,%2,%3}, [%4];" \
                 : "=r"((r)[0]), "=r"((r)[1]), "=r"((r)[2]), "=r"((r)[3]) : "r"(a))

// ======================= prep kernels =======================
__global__ void prep_nv(const float* __restrict__ v, const float* __restrict__ g) {
    __shared__ float red[16];
    __shared__ float s_norm;
    int tid = threadIdx.x;                 // 512 threads
    float x = v[tid];
    float sq = x * x;
    #pragma unroll
    for (int o = 16; o > 0; o >>= 1) sq += __shfl_xor_sync(0xffffffffu, sq, o);
    if ((tid & 31) == 0) red[tid >> 5] = sq;
    __syncthreads();
    if (tid < 32) {
        float t = (tid < 16) ? red[tid] : 0.f;
        #pragma unroll
        for (int o = 8; o > 0; o >>= 1) t += __shfl_xor_sync(0xffffffffu, t, o);
        if (tid == 0) s_norm = sqrtf(t);
    }
    __syncthreads();
    g_nv[tid] = g[0] * x / s_norm;
}

__global__ void prep_pqb(const float* __restrict__ query, const float* __restrict__ Wq,
                         const float* __restrict__ bias) {
    __shared__ float q[E_DIM];
    int b = blockIdx.x, e = threadIdx.x;   // 64 blocks x 512 threads
    q[e] = query[b * 512 + e];
    __syncthreads();
    const float4* W4 = reinterpret_cast<const float4*>(Wq + e * 512);
    float acc = 0.f;
    #pragma unroll 16
    for (int k = 0; k < 128; k++) {
        float4 w = W4[k];
        acc += q[4 * k] * w.x + q[4 * k + 1] * w.y + q[4 * k + 2] * w.z + q[4 * k + 3] * w.w;
    }
    g_pqb[b * 512 + e] = acc + bias[e];
}

__global__ void prep_wvb(const float* __restrict__ Wv) {
    int i = blockIdx.x * 1024 + threadIdx.x;   // 256 blocks x 1024
    g_WvB[i] = __float2bfloat16_rn(Wv[i]);
}

// ======================= score kernel (ldmatrix + mma.sync) =======================
// CTA = 128 rows of [S*B, 512] (2 s-values). 16 warps: 4(M) x 4(N), warp tile 32x32.
// A resident: [128][520] bf16 = 133120 B. B ring: 3 x [128][72] bf16 = 55296 B.
#define AS_STRIDE 1040          // bytes per A row (520 bf16)
#define BS_STRIDE 144           // bytes per B row (72 bf16)
#define BS_SLOT   18432         // 128 * 144
#define SM_A   0
#define SM_B   133120
#define SM_SSC 188416
#define SM_TOT 188928

__device__ __forceinline__ void load_B_chunk(uint32_t sb, int g, int tid) {
    const int nt = g >> 3, kc = g & 7, slot = g % 3;
    const __nv_bfloat16* src = g_WvB + (size_t)(nt * 128) * 512 + kc * 64;
    uint32_t dbase = sb + SM_B + slot * BS_SLOT;
    #pragma unroll
    for (int t = 0; t < 2; t++) {
        int idx = tid + 512 * t;          // 0..1023 granules of 16B
        int row = idx >> 3, gc = idx & 7;
        cpa16(dbase + row * BS_STRIDE + gc * 16, src + (size_t)row * 512 + gc * 8);
    }
    asm volatile("cp.async.commit_group;" ::: "memory");
}

__global__ __launch_bounds__(512, 1) void score_mma(const float* __restrict__ value) {
    extern __shared__ unsigned char smem[];
    uint32_t sb = smem_u32(smem);
    const int tid = threadIdx.x;
    const int l   = tid & 31, wid = tid >> 5;
    const int wm  = wid & 3, wn = wid >> 2;     // 4 M-warps x 4 N-warps
    const int lr  = l & 7, q = l >> 3;
    const int l4  = l >> 2, lm = l & 3;
    const int blk = blockIdx.x;
    float* ssc = reinterpret_cast<float*>(smem + SM_SSC);

    // prefetch first two B chunks (overlap A load)
    load_B_chunk(sb, 0, tid);
    load_B_chunk(sb, 1, tid);

    // Load A = value rows [blk*128, +128), f32 -> bf16, padded rows
    {
        const float4* V4 = reinterpret_cast<const float4*>(value) + (size_t)blk * 16384;
        #pragma unroll 8
        for (int j = 0; j < 32; j++) {
            int i = tid + 512 * j;            // float4 idx; 128 per row
            float4 f = V4[i];
            int row = i >> 7, c4 = i & 127;
            uint2 u; u.x = pk2(f.x, f.y); u.y = pk2(f.z, f.w);
            *reinterpret_cast<uint2*>(smem + SM_A + row * AS_STRIDE + c4 * 8) = u;
        }
    }
    if (tid < 128) ssc[tid] = 0.f;

    // per-lane ldmatrix base addresses
    // A x4: {m0-7,k0-7},{m8-15,k0-7},{m0-7,k8-15},{m8-15,k8-15} -> row += (q&1)*8, k += (q>>1)*8
    uint32_t aBase = sb + SM_A + (uint32_t)(wm * 32 + (q & 1) * 8 + lr) * AS_STRIDE + (q >> 1) * 16;
    // B x4: {n0-7,k0-7},{n0-7,k8-15},{n8-15,k0-7},{n8-15,k8-15} -> row += (q>>1)*8, k += (q&1)*8
    uint32_t bBase = sb + SM_B + (uint32_t)(wn * 32 + (q >> 1) * 8 + lr) * BS_STRIDE + (q & 1) * 16;

    float part[2][2];
    part[0][0] = part[0][1] = part[1][0] = part[1][1] = 0.f;
    float acc[2][4][4];

    for (int g = 0; g < 32; g++) {
        const int kc = g & 7, nt = g >> 3;
        if (g < 31) asm volatile("cp.async.wait_group 1;" ::: "memory");
        else        asm volatile("cp.async.wait_group 0;" ::: "memory");
        __syncthreads();
        if (g + 2 < 32) load_B_chunk(sb, g + 2, tid);

        if (kc == 0) {
            #pragma unroll
            for (int mf = 0; mf < 2; mf++)
                #pragma unroll
                for (int nf = 0; nf < 4; nf++)
                    #pragma unroll
                    for (int qq = 0; qq < 4; qq++) acc[mf][nf][qq] = 0.f;
        }

        uint32_t aK = aBase + kc * 128;                 // 64 k = 128 B
        uint32_t bS = bBase + (uint32_t)(g % 3) * BS_SLOT;
        #pragma unroll
        for (int kk = 0; kk < 4; kk++) {
            unsigned bf[2][4], af[2][4];
            LDSM4(bf[0], bS + kk * 32);
            LDSM4(bf[1], bS + 16 * BS_STRIDE + kk * 32);
            LDSM4(af[0], aK + kk * 32);
            LDSM4(af[1], aK + 16 * AS_STRIDE + kk * 32);
            #pragma unroll
            for (int mf = 0; mf < 2; mf++)
                #pragma unroll
                for (int nf = 0; nf < 4; nf++)
                    mma_bf16(acc[mf][nf], af[mf], bf[nf >> 1][(nf & 1) * 2], bf[nf >> 1][(nf & 1) * 2 + 1]);
        }

        if (kc == 7) {
            // epilogue for this n-tile: tanh(key + pq) . nv -> per-row partials (regs only)
            #pragma unroll
            for (int mf = 0; mf < 2; mf++) {
                int r0 = wm * 32 + mf * 16 + l4;
                const float* pq0 = g_pqb + (size_t)(r0 & 63) * 512;
                const float* pq1 = g_pqb + (size_t)((r0 + 8) & 63) * 512;
                #pragma unroll
                for (int nf = 0; nf < 4; nf++) {
                    int e = nt * 128 + wn * 32 + nf * 8 + lm * 2;
                    float2 w  = *reinterpret_cast<const float2*>(g_nv + e);
                    float2 p0 = *reinterpret_cast<const float2*>(pq0 + e);
                    float2 p1 = *reinterpret_cast<const float2*>(pq1 + e);
                    part[mf][0] += w.x * tanh_fast(acc[mf][nf][0] + p0.x)
                                 + w.y * tanh_fast(acc[mf][nf][1] + p0.y);
                    part[mf][1] += w.x * tanh_fast(acc[mf][nf][2] + p1.x)
                                 + w.y * tanh_fast(acc[mf][nf][3] + p1.y);
                }
            }
        }
    }

    // reduce across quad lanes (cols), then across N-warps via smem atomics
    #pragma unroll
    for (int mf = 0; mf < 2; mf++)
        #pragma unroll
        for (int rr = 0; rr < 2; rr++) {
            float p = part[mf][rr];
            p += __shfl_xor_sync(0xffffffffu, p, 1);
            p += __shfl_xor_sync(0xffffffffu, p, 2);
            if (lm == 0) atomicAdd(&ssc[wm * 32 + mf * 16 + rr * 8 + l4], p);
        }
    __syncthreads();
    if (tid < 128) {
        int b = tid & 63, sl = tid >> 6;    // global row = blk*128 + tid -> s = blk*2+sl, b
        g_scores[(size_t)b * 4096 + blk * 2 + sl] = ssc[tid];
    }
}

// ======================= softmax over s, per b (also zeroes ctx region) =======================
__global__ void softmax_kernel(const unsigned char* __restrict__ mask, float* __restrict__ out) {
    __shared__ float red[8];
    int b = blockIdx.x, tid = threadIdx.x;   // 64 blocks x 256
    // zero this b's context slice (out[0 : 64*512])
    out[b * 512 + tid] = 0.f;
    out[b * 512 + 256 + tid] = 0.f;
    const float* sc = g_scores + (size_t)b * 4096;
    float lv[16];
    float mx = -INFINITY;
    #pragma unroll
    for (int j = 0; j < 16; j++) {
        int s = tid + 256 * j;
        float v = sc[s];
        if (mask[s * 64 + b]) v = -INFINITY;
        lv[j] = v;
        mx = fmaxf(mx, v);
    }
    #pragma unroll
    for (int o = 16; o > 0; o >>= 1) mx = fmaxf(mx, __shfl_xor_sync(0xffffffffu, mx, o));
    if ((tid & 31) == 0) red[tid >> 5] = mx;
    __syncthreads();
    mx = red[0];
    #pragma unroll
    for (int w = 1; w < 8; w++) mx = fmaxf(mx, red[w]);
    float sum = 0.f;
    #pragma unroll
    for (int j = 0; j < 16; j++) { float e = __expf(lv[j] - mx); lv[j] = e; sum += e; }
    #pragma unroll
    for (int o = 16; o > 0; o >>= 1) sum += __shfl_xor_sync(0xffffffffu, sum, o);
    __syncthreads();
    if ((tid & 31) == 0) red[tid >> 5] = sum;
    __syncthreads();
    sum = 0.f;
    #pragma unroll
    for (int w = 0; w < 8; w++) sum += red[w];
    float inv = 1.f / sum;
    #pragma unroll
    for (int j = 0; j < 16; j++) {
        int s = tid + 256 * j;
        float p = lv[j] * inv;
        out[32768 + s * 64 + b] = p;            // attn copy 1 [s][b]
        out[294912 + s * 64 + b] = p;           // attn copy 2 [s][b]
        g_attn_bs[(size_t)b * 4096 + s] = p;    // [b][s] for context
    }
}

// ======================= context =======================
__global__ void context_kernel(const float* __restrict__ value, float* __restrict__ ctx) {
    int b = blockIdx.x, ch = blockIdx.y, tid = threadIdx.x;   // (64,8) x 128
    const float4* V4 = reinterpret_cast<const float4*>(value);
    const float* attn = g_attn_bs + (size_t)b * 4096;
    float4 acc = make_float4(0.f, 0.f, 0.f, 0.f);
    int s0 = ch * 512;
    #pragma unroll 8
    for (int s = s0; s < s0 + 512; s++) {
        float p = __ldg(&attn[s]);
        float4 v = V4[(size_t)(s * 64 + b) * 128 + tid];
        acc.x += p * v.x; acc.y += p * v.y; acc.z += p * v.z; acc.w += p * v.w;
    }
    float* c = ctx + b * 512 + tid * 4;
    atomicAdd(c + 0, acc.x); atomicAdd(c + 1, acc.y);
    atomicAdd(c + 2, acc.z); atomicAdd(c + 3, acc.w);
}

// ======================= launch =======================
extern "C" void kernel_launch(void* const* d_in, const int* in_sizes, int n_in,
                              void* d_out, int out_size) {
    const float* query        = (const float*)d_in[0];
    const float* value        = (const float*)d_in[1];
    const unsigned char* mask = (const unsigned char*)d_in[2];
    const float* Wq           = (const float*)d_in[3];
    const float* Wv           = (const float*)d_in[4];
    const float* v            = (const float*)d_in[5];
    const float* bias         = (const float*)d_in[6];
    const float* g            = (const float*)d_in[7];
    float* out = (float*)d_out;

    cudaFuncSetAttribute(score_mma, cudaFuncAttributeMaxDynamicSharedMemorySize, SM_TOT);

    prep_nv<<<1, 512>>>(v, g);
    prep_pqb<<<64, 512>>>(query, Wq, bias);
    prep_wvb<<<256, 1024>>>(Wv);
    score_mma<<<2048, 512, SM_TOT>>>(value);
    softmax_kernel<<<64, 256>>>(mask, out);
    context_kernel<<<dim3(64, 8), 128>>>(value, out);
}

// round 13
// speedup vs baseline: 1.0431x; 1.0431x over previous
#include <cuda_runtime.h>
#include <cuda_bf16.h>
#include <math.h>
#include <cstdint>

#define S_DIM 4096
#define B_DIM 64
#define E_DIM 512
#define V_DIM 512

// Scratch (allocation-free rule: __device__ globals)
__device__ float g_scores[B_DIM * S_DIM];     // [b][s]
__device__ float g_attn_bs[B_DIM * S_DIM];    // [b][s]
__device__ __align__(16) float g_pqb[B_DIM * E_DIM];
__device__ __align__(16) float g_nv[E_DIM];
__device__ __align__(128) __nv_bfloat16 g_WvB[E_DIM * V_DIM];

// ======================= helpers =======================
__device__ __forceinline__ uint32_t smem_u32(const void* p) {
    uint32_t a;
    asm("{ .reg .u64 t; cvta.to.shared.u64 t, %1; cvt.u32.u64 %0, t; }" : "=r"(a) : "l"(p));
    return a;
}
__device__ __forceinline__ float tanh_fast(float x) {
    float y; asm("tanh.approx.f32 %0, %1;" : "=f"(y) : "f"(x)); return y;
}
__device__ __forceinline__ unsigned pk2(float x, float y) {
    __nv_bfloat162 h = __floats2bfloat162_rn(x, y);
    return reinterpret_cast<unsigned&>(h);
}
__device__ __forceinline__ void cpa16(uint32_t dst, const void* src) {
    asm volatile("cp.async.cg.shared.global [%0], [%1], 16;" :: "r"(dst), "l"(src) : "memory");
}
__device__ __forceinline__ void mma_bf16(float c[4], const unsigned a[4], unsigned b0, unsigned b1) {
    asm volatile("mma.sync.aligned.m16n8k16.row.col.f32.bf16.bf16.f32 "
                 "{%0,%1,%2,%3}, {%4,%5,%6,%7}, {%8,%9}, {%0,%1,%2,%3};"
                 : "+f"(c[0]), "+f"(c[1]), "+f"(c[2]), "+f"(c[3])
                 : "r"(a[0]), "r"(a[1]), "r"(a[2]), "r"(a[3]), "r"(b0), "r"(b1));
}
#define LDSM4(r, a) \
    asm volatile("ldmatrix.sync.aligned.m8n8.x4.shared.b16 {%0,%1,%2,%3}, [%4];" \
                 : "=r"((r)[0]), "=r"((r)[1]), "=r"((r)[2]), "=r"((r)[3]) : "r"(a))

// ======================= prep kernels =======================
__global__ void prep_nv(const float* __restrict__ v, const float* __restrict__ g) {
    __shared__ float red[16];
    __shared__ float s_norm;
    int tid = threadIdx.x;                 // 512 threads
    float x = v[tid];
    float sq = x * x;
    #pragma unroll
    for (int o = 16; o > 0; o >>= 1) sq += __shfl_xor_sync(0xffffffffu, sq, o);
    if ((tid & 31) == 0) red[tid >> 5] = sq;
    __syncthreads();
    if (tid < 32) {
        float t = (tid < 16) ? red[tid] : 0.f;
        #pragma unroll
        for (int o = 8; o > 0; o >>= 1) t += __shfl_xor_sync(0xffffffffu, t, o);
        if (tid == 0) s_norm = sqrtf(t);
    }
    __syncthreads();
    g_nv[tid] = g[0] * x / s_norm;
}

__global__ void prep_pqb(const float* __restrict__ query, const float* __restrict__ Wq,
                         const float* __restrict__ bias) {
    __shared__ float q[E_DIM];
    int b = blockIdx.x, e = threadIdx.x;   // 64 blocks x 512 threads
    q[e] = query[b * 512 + e];
    __syncthreads();
    const float4* W4 = reinterpret_cast<const float4*>(Wq + e * 512);
    float acc = 0.f;
    #pragma unroll 16
    for (int k = 0; k < 128; k++) {
        float4 w = W4[k];
        acc += q[4 * k] * w.x + q[4 * k + 1] * w.y + q[4 * k + 2] * w.z + q[4 * k + 3] * w.w;
    }
    g_pqb[b * 512 + e] = acc + bias[e];
}

__global__ void prep_wvb(const float* __restrict__ Wv) {
    int i = blockIdx.x * 1024 + threadIdx.x;   // 256 blocks x 1024
    g_WvB[i] = __float2bfloat16_rn(Wv[i]);
}

// ======================= score kernel =======================
// CTA = 64 rows (1 s-value), 256 threads, 8 warps: 2(M) x 4(N), warp tile 32x32.
// 2 CTAs resident per SM -> cross-CTA latency hiding of the barrier convoy.
// A resident: [64][520] bf16 = 66560 B. B double-buffer: 2 x [128][72] bf16 = 36864 B.
// Total smem = 66560 + 36864 + 256 = 103680 B  (<= 114KB -> 2 CTAs/SM).
#define AS_STRIDE 1040          // bytes per A row (520 bf16)
#define BS_STRIDE 144           // bytes per B row (72 bf16)
#define BS_SLOT   18432         // 128 * 144
#define SM_A   0
#define SM_B   66560
#define SM_SSC 103424
#define SM_TOT 103680

__device__ __forceinline__ void load_B_chunk(uint32_t sb, int g, int tid) {
    const int nt = g >> 3, kc = g & 7, slot = g & 1;
    const __nv_bfloat16* src = g_WvB + (size_t)(nt * 128) * 512 + kc * 64;
    uint32_t dbase = sb + SM_B + slot * BS_SLOT;
    #pragma unroll
    for (int t = 0; t < 4; t++) {
        int idx = tid + 256 * t;          // 0..1023 granules of 16B
        int row = idx >> 3, gc = idx & 7;
        cpa16(dbase + row * BS_STRIDE + gc * 16, src + (size_t)row * 512 + gc * 8);
    }
    asm volatile("cp.async.commit_group;" ::: "memory");
}

__global__ __launch_bounds__(256, 2) void score_mma(const float* __restrict__ value) {
    extern __shared__ unsigned char smem[];
    uint32_t sb = smem_u32(smem);
    const int tid = threadIdx.x;
    const int l   = tid & 31, wid = tid >> 5;
    const int wm  = wid & 1, wn = wid >> 1;     // 2 M-warps x 4 N-warps
    const int lr  = l & 7, q = l >> 3;
    const int l4  = l >> 2, lm = l & 3;
    const int blk = blockIdx.x;                 // s = blk
    float* ssc = reinterpret_cast<float*>(smem + SM_SSC);

    // prefetch first B chunk (overlaps A load)
    load_B_chunk(sb, 0, tid);

    // Load A = value rows of s=blk (64 x 512 f32) -> bf16, padded rows
    {
        const float4* V4 = reinterpret_cast<const float4*>(value) + (size_t)blk * 8192;
        #pragma unroll 8
        for (int j = 0; j < 32; j++) {
            int i = tid + 256 * j;            // float4 idx; 128 per row
            float4 f = V4[i];
            int row = i >> 7, c4 = i & 127;
            uint2 u; u.x = pk2(f.x, f.y); u.y = pk2(f.z, f.w);
            *reinterpret_cast<uint2*>(smem + SM_A + row * AS_STRIDE + c4 * 8) = u;
        }
    }
    if (tid < 64) ssc[tid] = 0.f;

    // per-lane ldmatrix base addresses
    // A x4: {m0-7,k0-7},{m8-15,k0-7},{m0-7,k8-15},{m8-15,k8-15} -> row += (q&1)*8, k += (q>>1)*8
    uint32_t aBase = sb + SM_A + (uint32_t)(wm * 32 + (q & 1) * 8 + lr) * AS_STRIDE + (q >> 1) * 16;
    // B x4: {n0-7,k0-7},{n0-7,k8-15},{n8-15,k0-7},{n8-15,k8-15} -> row += (q>>1)*8, k += (q&1)*8
    uint32_t bBase = sb + SM_B + (uint32_t)(wn * 32 + (q >> 1) * 8 + lr) * BS_STRIDE + (q & 1) * 16;

    float part[2][2];
    part[0][0] = part[0][1] = part[1][0] = part[1][1] = 0.f;
    float acc[2][4][4];

    for (int g = 0; g < 32; g++) {
        const int kc = g & 7, nt = g >> 3;
        asm volatile("cp.async.wait_group 0;" ::: "memory");
        __syncthreads();
        if (g + 1 < 32) load_B_chunk(sb, g + 1, tid);

        if (kc == 0) {
            #pragma unroll
            for (int mf = 0; mf < 2; mf++)
                #pragma unroll
                for (int nf = 0; nf < 4; nf++)
                    #pragma unroll
                    for (int qq = 0; qq < 4; qq++) acc[mf][nf][qq] = 0.f;
        }

        uint32_t aK = aBase + kc * 128;                 // 64 k = 128 B
        uint32_t bS = bBase + (uint32_t)(g & 1) * BS_SLOT;
        #pragma unroll
        for (int kk = 0; kk < 4; kk++) {
            unsigned bf[2][4], af[2][4];
            LDSM4(bf[0], bS + kk * 32);
            LDSM4(bf[1], bS + 16 * BS_STRIDE + kk * 32);
            LDSM4(af[0], aK + kk * 32);
            LDSM4(af[1], aK + 16 * AS_STRIDE + kk * 32);
            #pragma unroll
            for (int mf = 0; mf < 2; mf++)
                #pragma unroll
                for (int nf = 0; nf < 4; nf++)
                    mma_bf16(acc[mf][nf], af[mf], bf[nf >> 1][(nf & 1) * 2], bf[nf >> 1][(nf & 1) * 2 + 1]);
        }

        if (kc == 7) {
            // epilogue for this n-tile: tanh(key + pq) . nv -> per-row partials (regs only)
            #pragma unroll
            for (int mf = 0; mf < 2; mf++) {
                int r0 = wm * 32 + mf * 16 + l4;        // row in 0..63 == b
                const float* pq0 = g_pqb + (size_t)r0 * 512;
                const float* pq1 = g_pqb + (size_t)(r0 + 8) * 512;
                #pragma unroll
                for (int nf = 0; nf < 4; nf++) {
                    int e = nt * 128 + wn * 32 + nf * 8 + lm * 2;
                    float2 w  = *reinterpret_cast<const float2*>(g_nv + e);
                    float2 p0 = *reinterpret_cast<const float2*>(pq0 + e);
                    float2 p1 = *reinterpret_cast<const float2*>(pq1 + e);
                    part[mf][0] += w.x * tanh_fast(acc[mf][nf][0] + p0.x)
                                 + w.y * tanh_fast(acc[mf][nf][1] + p0.y);
                    part[mf][1] += w.x * tanh_fast(acc[mf][nf][2] + p1.x)
                                 + w.y * tanh_fast(acc[mf][nf][3] + p1.y);
                }
            }
        }
    }

    // reduce across quad lanes (cols), then across N-warps via smem atomics
    #pragma unroll
    for (int mf = 0; mf < 2; mf++)
        #pragma unroll
        for (int rr = 0; rr < 2; rr++) {
            float p = part[mf][rr];
            p += __shfl_xor_sync(0xffffffffu, p, 1);
            p += __shfl_xor_sync(0xffffffffu, p, 2);
            if (lm == 0) atomicAdd(&ssc[wm * 32 + mf * 16 + rr * 8 + l4], p);
        }
    __syncthreads();
    if (tid < 64) {
        // row tid == b ; s = blk
        g_scores[(size_t)tid * 4096 + blk] = ssc[tid];
    }
}

// ======================= softmax over s, per b (also zeroes ctx region) =======================
__global__ void softmax_kernel(const unsigned char* __restrict__ mask, float* __restrict__ out) {
    __shared__ float red[8];
    int b = blockIdx.x, tid = threadIdx.x;   // 64 blocks x 256
    out[b * 512 + tid] = 0.f;
    out[b * 512 + 256 + tid] = 0.f;
    const float* sc = g_scores + (size_t)b * 4096;
    float lv[16];
    float mx = -INFINITY;
    #pragma unroll
    for (int j = 0; j < 16; j++) {
        int s = tid + 256 * j;
        float v = sc[s];
        if (mask[s * 64 + b]) v = -INFINITY;
        lv[j] = v;
        mx = fmaxf(mx, v);
    }
    #pragma unroll
    for (int o = 16; o > 0; o >>= 1) mx = fmaxf(mx, __shfl_xor_sync(0xffffffffu, mx, o));
    if ((tid & 31) == 0) red[tid >> 5] = mx;
    __syncthreads();
    mx = red[0];
    #pragma unroll
    for (int w = 1; w < 8; w++) mx = fmaxf(mx, red[w]);
    float sum = 0.f;
    #pragma unroll
    for (int j = 0; j < 16; j++) { float e = __expf(lv[j] - mx); lv[j] = e; sum += e; }
    #pragma unroll
    for (int o = 16; o > 0; o >>= 1) sum += __shfl_xor_sync(0xffffffffu, sum, o);
    __syncthreads();
    if ((tid & 31) == 0) red[tid >> 5] = sum;
    __syncthreads();
    sum = 0.f;
    #pragma unroll
    for (int w = 0; w < 8; w++) sum += red[w];
    float inv = 1.f / sum;
    #pragma unroll
    for (int j = 0; j < 16; j++) {
        int s = tid + 256 * j;
        float p = lv[j] * inv;
        out[32768 + s * 64 + b] = p;            // attn copy 1 [s][b]
        out[294912 + s * 64 + b] = p;           // attn copy 2 [s][b]
        g_attn_bs[(size_t)b * 4096 + s] = p;    // [b][s] for context
    }
}

// ======================= context =======================
__global__ void context_kernel(const float* __restrict__ value, float* __restrict__ ctx) {
    int b = blockIdx.x, ch = blockIdx.y, tid = threadIdx.x;   // (64,8) x 128
    const float4* V4 = reinterpret_cast<const float4*>(value);
    const float* attn = g_attn_bs + (size_t)b * 4096;
    float4 acc = make_float4(0.f, 0.f, 0.f, 0.f);
    int s0 = ch * 512;
    #pragma unroll 8
    for (int s = s0; s < s0 + 512; s++) {
        float p = __ldg(&attn[s]);
        float4 v = V4[(size_t)(s * 64 + b) * 128 + tid];
        acc.x += p * v.x; acc.y += p * v.y; acc.z += p * v.z; acc.w += p * v.w;
    }
    float* c = ctx + b * 512 + tid * 4;
    atomicAdd(c + 0, acc.x); atomicAdd(c + 1, acc.y);
    atomicAdd(c + 2, acc.z); atomicAdd(c + 3, acc.w);
}

// ======================= launch =======================
extern "C" void kernel_launch(void* const* d_in, const int* in_sizes, int n_in,
                              void* d_out, int out_size) {
    const float* query        = (const float*)d_in[0];
    const float* value        = (const float*)d_in[1];
    const unsigned char* mask = (const unsigned char*)d_in[2];
    const float* Wq           = (const float*)d_in[3];
    const float* Wv           = (const float*)d_in[4];
    const float* v            = (const float*)d_in[5];
    const float* bias         = (const float*)d_in[6];
    const float* g            = (const float*)d_in[7];
    float* out = (float*)d_out;

    cudaFuncSetAttribute(score_mma, cudaFuncAttributeMaxDynamicSharedMemorySize, SM_TOT);

    prep_nv<<<1, 512>>>(v, g);
    prep_pqb<<<64, 512>>>(query, Wq, bias);
    prep_wvb<<<256, 1024>>>(Wv);
    score_mma<<<4096, 256, SM_TOT>>>(value);
    softmax_kernel<<<64, 256>>>(mask, out);
    context_kernel<<<dim3(64, 8), 128>>>(value, out);
}